// round 16
// baseline (speedup 1.0000x reference)
#include <cuda_runtime.h>
#include <cstdint>

// Problem constants (fixed by the reference).
#define ROWS       8192
#define COLS       8192
#define NUMEL      (1ULL * ROWS * COLS)          // 64M output floats
#define NCODES     (NUMEL / 4)                   // 16M codes (centroid_len = 4)
#define CB_ENTRIES 512                           // 2 codebooks * 256 centroids (float4)

#define BLOCK      128
#define CPT        4                               // codes per thread per tile
#define TILE_CODES (BLOCK * CPT)                   // 512 codes
#define TILE_BYTES (TILE_CODES * 16)               // 8 KB output per tile
#define NTILES     ((int)(NCODES / TILE_CODES))    // 32768 (exact)
#define DEPTH      2
#define GRID       (152 * 9)                       // 1368 blocks (24KB smem -> 9/SM)

// R8 structure re-tuned for more independent pipelines per SM:
//  - 8KB output tiles (single contiguous cp.async.bulk burst each)
//  - BLOCK=128 -> 24KB smem/block -> 9 block-pipelines per SM (vs R8's 5)
//  - narrower barriers (4 warps) cut BAR cost and straggler coupling
// More phase-decorrelated request streams per SM keep DRAM busy through
// read/write turnaround gaps.

__device__ __forceinline__ uint32_t smem_u32(const void* p) {
    uint32_t a;
    asm("{ .reg .u64 t; cvta.to.shared.u64 t, %1; cvt.u32.u64 %0, t; }"
        : "=r"(a) : "l"(p));
    return a;
}

__global__ __launch_bounds__(BLOCK) void dequant_kernel(
    const float4* __restrict__ codebooks,   // [512] float4
    const float*  __restrict__ scales,      // [NUMEL/64]
    const int*    __restrict__ codes,       // [NCODES]
    float4*       __restrict__ out4)        // [NCODES]
{
    __shared__ float4 s_cb[CB_ENTRIES];                        // 8 KB
    __shared__ __align__(128) float4 s_out[DEPTH][TILE_CODES]; // 2 x 8 KB

    for (int i = threadIdx.x; i < CB_ENTRIES; i += BLOCK)
        s_cb[i] = codebooks[i];
    __syncthreads();

    const int t      = threadIdx.x;
    const int stride = gridDim.x;

    int iter = 0;
    for (int tile = blockIdx.x; tile < NTILES; tile += stride, iter++) {
        const int buf = iter & 1;
        const long long base = (long long)tile * TILE_CODES;
        // First 16384 tiles lie entirely in codebook 0, rest in codebook 1.
        const int cb_off = (tile >= (NTILES / 2)) ? 256 : 0;

        const int*   cp = codes  + base;
        const float* sp = scales + (base >> 4);

        // Front-batch global loads (all in flight across the barrier below).
        int   c[CPT];
        float s[CPT];
        #pragma unroll
        for (int k = 0; k < CPT; k++)
            c[k] = __ldg(cp + k * BLOCK + t);
        #pragma unroll
        for (int k = 0; k < CPT; k++)
            s[k] = __ldg(sp + ((k * BLOCK + t) >> 4));

        // Ensure the TMA store issued 2 iterations ago (same buffer) has
        // finished READING this smem buffer before we overwrite it.
        if (t == 0)
            asm volatile("cp.async.bulk.wait_group.read %0;" :: "n"(DEPTH - 1) : "memory");
        __syncthreads();

        // Gather + scale -> smem tile (interleaved STS.128, conflict-free).
        #pragma unroll
        for (int k = 0; k < CPT; k++) {
            float4 v = s_cb[cb_off + c[k]];
            v.x *= s[k]; v.y *= s[k]; v.z *= s[k]; v.w *= s[k];
            s_out[buf][k * BLOCK + t] = v;
        }
        __syncthreads();

        // One thread issues the bulk async store of the whole 8KB tile.
        if (t == 0) {
            asm volatile("fence.proxy.async.shared::cta;" ::: "memory");
            asm volatile(
                "cp.async.bulk.global.shared::cta.bulk_group [%0], [%1], %2;"
                :: "l"(out4 + base), "r"(smem_u32(&s_out[buf][0])), "n"(TILE_BYTES)
                : "memory");
            asm volatile("cp.async.bulk.commit_group;" ::: "memory");
        }
    }

    // Drain all outstanding bulk stores before exit.
    if (t == 0)
        asm volatile("cp.async.bulk.wait_group 0;" ::: "memory");
}

extern "C" void kernel_launch(void* const* d_in, const int* in_sizes, int n_in,
                              void* d_out, int out_size)
{
    // metadata order: codebooks [2,256,4] f32, scales [1M,1] f32, codes [2,8M] i32, rows, columns
    const float4* codebooks = (const float4*)d_in[0];
    const float*  scales    = (const float*)d_in[1];
    const int*    codes     = (const int*)d_in[2];
    float4*       out4      = (float4*)d_out;

    int grid = GRID;
    if (grid > NTILES) grid = NTILES;

    dequant_kernel<<<grid, BLOCK>>>(codebooks, scales, codes, out4);
}